// round 5
// baseline (speedup 1.0000x reference)
#include <cuda_runtime.h>
#include <cstdint>

#define NP 4194304      // TOTAL_PULSES
#define ND 262144       // NUM_DOMS
#define DD 64           // EMBED_DIM

// ---------------- persistent scratch (static device arrays; no allocs) ----------------
__device__ unsigned g_count[ND];
__device__ unsigned g_cursor[ND];
__device__ unsigned g_sorted[NP];
__device__ float    g_pooled[(size_t)ND * 128];   // [dom][0:64)=mean, [64:128)=max
__device__ unsigned g_total;
__device__ int      g_is64;

typedef unsigned long long ull;

// ---------------- packed f32x2 helpers (FFMA2: 2x scalar FFMA throughput) -------------
__device__ __forceinline__ ull pk2(float x) {
    ull r; asm("mov.b64 %0, {%1, %1};" : "=l"(r) : "f"(x)); return r;
}
__device__ __forceinline__ void fma2(ull& d, ull a, ull b) {
    asm("fma.rn.f32x2 %0, %1, %2, %0;" : "+l"(d) : "l"(a), "l"(b));
}
__device__ __forceinline__ ull add2(ull a, ull b) {
    ull r; asm("add.rn.f32x2 %0, %1, %2;" : "=l"(r) : "l"(a), "l"(b)); return r;
}

// Load dom index i, robust to idx buffer being int32 or int64.
__device__ __forceinline__ int load_dom(const int* __restrict__ idx32, int i) {
    int d;
    if (g_is64) d = (int)((const long long*)idx32)[i];
    else        d = idx32[i];
    return d & (ND - 1);   // indices are guaranteed < ND; mask = crash-proofing only
}

// ---------------- K-1: detect index dtype ----------------
// int64 data: high word of element k is at 32-bit word 2k+1 and is always 0
// (all indices < 2^18). int32 data: those words are uniform dom ids.
// All sampled word indices < NP, in-bounds for both layouts.
__global__ void k_detect(const int* __restrict__ idx32) {
    __shared__ int any;
    if (threadIdx.x == 0) any = 0;
    __syncthreads();
    int nz = 0;
#pragma unroll
    for (int s = 0; s < 8; s++) {
        unsigned k = (unsigned)(threadIdx.x * 8 + s) * 1024u;  // k < NP/2
        nz |= idx32[2u * k + 1u];
    }
    if (nz) atomicOr(&any, 1);
    __syncthreads();
    if (threadIdx.x == 0) g_is64 = (any == 0);
}

// ---------------- K0: reset counts + global cursor ----------------
__global__ void k_init() {
    int i = blockIdx.x * blockDim.x + threadIdx.x;
    if (i < ND) g_count[i] = 0u;
    if (i == 0) g_total = 0u;
}

// ---------------- K1: histogram ----------------
__global__ void k_hist(const int* __restrict__ idx32) {
    int i = blockIdx.x * blockDim.x + threadIdx.x;
    atomicAdd(&g_count[load_dom(idx32, i)], 1u);
}

// ---------------- K2: per-block scan + atomic base (segment order is irrelevant) ------
__global__ void k_scan() {
    int i = blockIdx.x * 256 + threadIdx.x;
    int lane = threadIdx.x & 31, wid = threadIdx.x >> 5;
    unsigned c = g_count[i];
    unsigned v = c;
#pragma unroll
    for (int o = 1; o < 32; o <<= 1) {
        unsigned t = __shfl_up_sync(0xffffffffu, v, o);
        if (lane >= o) v += t;
    }
    __shared__ unsigned ws[8];
    __shared__ unsigned wbase;
    if (lane == 31) ws[wid] = v;
    __syncthreads();
    if (threadIdx.x == 0) {
        unsigned tot = 0;
#pragma unroll
        for (int w = 0; w < 8; w++) { unsigned t = ws[w]; ws[w] = tot; tot += t; }
        wbase = atomicAdd(&g_total, tot);
    }
    __syncthreads();
    g_cursor[i] = wbase + ws[wid] + (v - c);   // segment start; becomes end after K3
}

// ---------------- K3: bin-scatter pulse ids ----------------
__global__ void k_scatter(const int* __restrict__ idx32) {
    int i = blockIdx.x * blockDim.x + threadIdx.x;
    int d = load_dom(idx32, i);
    unsigned p = atomicAdd(&g_cursor[d], 1u);
    g_sorted[p] = (unsigned)i;
}

// ---------------- K4: warp-per-dom mean+max pooling ----------------
__global__ void k_pool(const float2* __restrict__ emb) {
    int dom  = blockIdx.x * 8 + (threadIdx.x >> 5);
    int lane = threadIdx.x & 31;
    unsigned c = g_count[dom];
    unsigned s = g_cursor[dom] - c;            // cursor == segment end after K3
    float2 sum = make_float2(0.f, 0.f);
    float2 mx  = make_float2(-3.402823466e38f, -3.402823466e38f);
    unsigned j = 0;
    for (; j + 4 <= c; j += 4) {               // MLP=4 row gather
        unsigned p0 = __ldg(&g_sorted[s + j + 0]);
        unsigned p1 = __ldg(&g_sorted[s + j + 1]);
        unsigned p2 = __ldg(&g_sorted[s + j + 2]);
        unsigned p3 = __ldg(&g_sorted[s + j + 3]);
        float2 e0 = __ldg(&emb[(size_t)p0 * 32 + lane]);
        float2 e1 = __ldg(&emb[(size_t)p1 * 32 + lane]);
        float2 e2 = __ldg(&emb[(size_t)p2 * 32 + lane]);
        float2 e3 = __ldg(&emb[(size_t)p3 * 32 + lane]);
        sum.x += (e0.x + e1.x) + (e2.x + e3.x);
        sum.y += (e0.y + e1.y) + (e2.y + e3.y);
        mx.x = fmaxf(fmaxf(fmaxf(mx.x, e0.x), fmaxf(e1.x, e2.x)), e3.x);
        mx.y = fmaxf(fmaxf(fmaxf(mx.y, e0.y), fmaxf(e1.y, e2.y)), e3.y);
    }
    for (; j < c; j++) {
        unsigned p0 = __ldg(&g_sorted[s + j]);
        float2 e0 = __ldg(&emb[(size_t)p0 * 32 + lane]);
        sum.x += e0.x; sum.y += e0.y;
        mx.x = fmaxf(mx.x, e0.x); mx.y = fmaxf(mx.y, e0.y);
    }
    float inv = c ? (1.f / (float)c) : 0.f;
    float2 mean = make_float2(sum.x * inv, sum.y * inv);
    if (!c) mx = make_float2(0.f, 0.f);        // empty segment: max := 0 (matches ref)
    float2* pool2 = (float2*)g_pooled;
    pool2[(size_t)dom * 64 + lane]      = mean; // k = 2*lane, 2*lane+1
    pool2[(size_t)dom * 64 + 32 + lane] = mx;   // k = 64 + 2*lane, ...
}

// ---------------- K5: pooled(256 doms x 128) @ W^T(128 x 64) + b, FFMA2 8x8 tile ------
__global__ void __launch_bounds__(256) k_gemm(const float* __restrict__ W,
                                              const float* __restrict__ B,
                                              float* __restrict__ out) {
    __shared__ float wT[128][64];   // wT[k][f] = W[f][k]
    __shared__ float aT[16][256];   // k-slab x doms (transposed)
    int t = threadIdx.x;
    int dom0 = blockIdx.x * 256;

    for (int i = t; i < 64 * 128; i += 256) {
        int f = i >> 7, k = i & 127;
        wT[k][f] = W[i];
    }

    int tx = t & 7;      // f-group: f = tx*8 .. tx*8+7
    int ty = t >> 3;     // dom-group: ty*8 .. ty*8+7 (within block)

    ull acc[8][4];
#pragma unroll
    for (int i = 0; i < 8; i++)
#pragma unroll
        for (int j = 0; j < 4; j++) acc[i][j] = 0ull;   // (+0,+0)

    const float4* src = (const float4*)(g_pooled + (size_t)(dom0 + t) * 128);

    for (int s = 0; s < 8; s++) {
        float4 v0 = __ldg(&src[s * 4 + 0]);
        float4 v1 = __ldg(&src[s * 4 + 1]);
        float4 v2 = __ldg(&src[s * 4 + 2]);
        float4 v3 = __ldg(&src[s * 4 + 3]);
        __syncthreads();    // prior compute done (also covers wT load at s=0)
        aT[0][t] = v0.x;  aT[1][t] = v0.y;  aT[2][t]  = v0.z;  aT[3][t]  = v0.w;
        aT[4][t] = v1.x;  aT[5][t] = v1.y;  aT[6][t]  = v1.z;  aT[7][t]  = v1.w;
        aT[8][t] = v2.x;  aT[9][t] = v2.y;  aT[10][t] = v2.z;  aT[11][t] = v2.w;
        aT[12][t] = v3.x; aT[13][t] = v3.y; aT[14][t] = v3.z;  aT[15][t] = v3.w;
        __syncthreads();
#pragma unroll
        for (int kk = 0; kk < 16; kk++) {
            int k = s * 16 + kk;
            float4 a0 = *(const float4*)&aT[kk][ty * 8];
            float4 a1 = *(const float4*)&aT[kk][ty * 8 + 4];
            ulonglong2 w0 = *(const ulonglong2*)&wT[k][tx * 8];
            ulonglong2 w1 = *(const ulonglong2*)&wT[k][tx * 8 + 4];
            ull ad[8] = { pk2(a0.x), pk2(a0.y), pk2(a0.z), pk2(a0.w),
                          pk2(a1.x), pk2(a1.y), pk2(a1.z), pk2(a1.w) };
#pragma unroll
            for (int i = 0; i < 8; i++) {
                fma2(acc[i][0], ad[i], w0.x);
                fma2(acc[i][1], ad[i], w0.y);
                fma2(acc[i][2], ad[i], w1.x);
                fma2(acc[i][3], ad[i], w1.y);
            }
        }
    }

    ulonglong2 b0 = *(const ulonglong2*)&B[tx * 8];
    ulonglong2 b1 = *(const ulonglong2*)&B[tx * 8 + 4];
    ull bp[4] = { b0.x, b0.y, b1.x, b1.y };
#pragma unroll
    for (int i = 0; i < 8; i++) {
        size_t d = (size_t)dom0 + (size_t)ty * 8 + i;
        ull* orow = (ull*)(out + d * 64 + tx * 8);
#pragma unroll
        for (int j = 0; j < 4; j++) orow[j] = add2(acc[i][j], bp[j]);
    }
}

// ---------------- launch ----------------
extern "C" void kernel_launch(void* const* d_in, const int* in_sizes, int n_in,
                              void* d_out, int out_size) {
    const float* emb = nullptr;
    const int*   idx = nullptr;   // int32 or int64 words; k_detect disambiguates
    const float* W   = nullptr;
    const float* B   = nullptr;
    for (int i = 0; i < n_in; i++) {
        int s = in_sizes[i];
        if      (s == NP * DD) emb = (const float*)d_in[i];
        else if (s == NP)      idx = (const int*)d_in[i];
        else if (s == DD * 2 * DD) W = (const float*)d_in[i];
        else if (s == DD)      B   = (const float*)d_in[i];
        // size-1 input is num_doms (compile-time constant here)
    }
    float* out = (float*)d_out;

    k_detect <<<1, 256>>>(idx);
    k_init   <<<ND / 256, 256>>>();
    k_hist   <<<NP / 256, 256>>>(idx);
    k_scan   <<<ND / 256, 256>>>();
    k_scatter<<<NP / 256, 256>>>(idx);
    k_pool   <<<ND / 8,   256>>>((const float2*)emb);
    k_gemm   <<<ND / 256, 256>>>(W, B, out);
}